// round 10
// baseline (speedup 1.0000x reference)
#include <cuda_runtime.h>

#define HBV   20
#define DV    40
#define WPAD  28             // weight row stride (floats), 112B, float4-aligned
#define EPB   32             // elements per block
#define LPE   10             // lanes per element (each lane owns cols 2q, 2q+1)
#define NTHR  320
#define CFP   21             // cfs float4 stride per element (84 words %32 = 20)
#define JJP   404            // jjs float stride per element (404 %32 = 20, 16B-mult)

// dynamic smem layout (float offsets)
#define OFF_SW1  0
#define OFF_SW2  560
#define OFF_SW3  1120
#define OFF_SW4  1680
#define OFF_P1S  2240        // [EPB][20]
#define OFF_S2S  2880        // [EPB][20]
#define OFF_CFS  3520        // float4[EPB*CFP]  (2688 floats)
#define OFF_JJS  6208        // float [EPB*JJP]  (12928 floats)
#define SMEM_FLOATS (OFF_JJS + EPB * JJP)      // 19136 floats = 76544 B

__global__ __launch_bounds__(NTHR, 3)
void ende_kernel(const float* __restrict__ x,
                 const float* __restrict__ w1g,
                 const float* __restrict__ w2g,
                 const float* __restrict__ w3g,
                 const float* __restrict__ w4g,
                 float* __restrict__ out_vec,
                 float* __restrict__ out_jt)
{
    extern __shared__ __align__(16) float smem[];
    float*  sw1 = smem + OFF_SW1;
    float*  sw2 = smem + OFF_SW2;
    float*  sw3 = smem + OFF_SW3;
    float*  sw4 = smem + OFF_SW4;
    float*  p1s = smem + OFF_P1S;
    float*  s2s = smem + OFF_S2S;
    float4* cfs = (float4*)(smem + OFF_CFS);
    float*  jjs = smem + OFF_JJS;

    const int tid = threadIdx.x;

    // Stage weights into padded smem (once per block)
    for (int idx = tid; idx < HBV * HBV; idx += NTHR) {
        int r = idx / HBV, cc = idx % HBV;
        sw1[r * WPAD + cc] = w1g[idx];
        sw2[r * WPAD + cc] = w2g[idx];
        sw3[r * WPAD + cc] = w3g[idx];
        sw4[r * WPAD + cc] = w4g[idx];
    }

    const int e  = tid / LPE;          // element slot within block
    const int q  = tid - e * LPE;
    const int c0 = 2 * q;              // this lane owns columns c0, c0+1
    const long long b = (long long)blockIdx.x * EPB + e;

    // ---- load x (two adjacent rows); publish p1 vector ----
    const float2 p1 = *(const float2*)(x + b * DV + c0);
    const float2 p2 = *(const float2*)(x + b * DV + HBV + c0);
    *(float2*)(p1s + e * HBV + c0) = p1;
    __syncthreads();

    // ---- Stage A: rows c0, c0+1 -> f1, f2 ----
    float e2x, e2y, s2x, s2y;
    {
        float a1x = 0.f, a1y = 0.f, a2x = 0.f, a2y = 0.f;
        const float4* rA0 = (const float4*)(sw1 + c0 * WPAD);
        const float4* rA1 = (const float4*)(sw1 + (c0 + 1) * WPAD);
        const float4* rB0 = (const float4*)(sw2 + c0 * WPAD);
        const float4* rB1 = (const float4*)(sw2 + (c0 + 1) * WPAD);
        const float4* pv  = (const float4*)(p1s + e * HBV);
        #pragma unroll
        for (int g = 0; g < 5; g++) {
            float4 P = pv[g];
            float4 A0 = rA0[g], A1 = rA1[g], B0 = rB0[g], B1 = rB1[g];
            a1x = fmaf(A0.x, P.x, a1x); a1x = fmaf(A0.y, P.y, a1x);
            a1x = fmaf(A0.z, P.z, a1x); a1x = fmaf(A0.w, P.w, a1x);
            a1y = fmaf(A1.x, P.x, a1y); a1y = fmaf(A1.y, P.y, a1y);
            a1y = fmaf(A1.z, P.z, a1y); a1y = fmaf(A1.w, P.w, a1y);
            a2x = fmaf(B0.x, P.x, a2x); a2x = fmaf(B0.y, P.y, a2x);
            a2x = fmaf(B0.z, P.z, a2x); a2x = fmaf(B0.w, P.w, a2x);
            a2y = fmaf(B1.x, P.x, a2y); a2y = fmaf(B1.y, P.y, a2y);
            a2y = fmaf(B1.z, P.z, a2y); a2y = fmaf(B1.w, P.w, a2y);
        }
        float f1x = tanhf(a1x), f1y = tanhf(a1y);
        float f2x = tanhf(a2x), f2y = tanhf(a2y);
        e2x = expf(f2x); e2y = expf(f2y);
        float p2ex = p2.x * e2x, p2ey = p2.y * e2y;
        s2x = p2ex + f1x; s2y = p2ey + f1y;
        *(float2*)(s2s + e * HBV + c0) = make_float2(s2x, s2y);
        *(float2*)((float*)(cfs + e * CFP + c0)) =
            make_float2(1.f - f1x * f1x, p2ex * (1.f - f2x * f2x));
        *(float2*)((float*)(cfs + e * CFP + c0 + 1)) =
            make_float2(1.f - f1y * f1y, p2ey * (1.f - f2y * f2y));
    }
    __syncthreads();

    // ---- Stage B: rows c0, c0+1 -> f3, f4; out vector ----
    float e4x, e4y;
    {
        float a3x = 0.f, a3y = 0.f, a4x = 0.f, a4y = 0.f;
        const float4* rA0 = (const float4*)(sw3 + c0 * WPAD);
        const float4* rA1 = (const float4*)(sw3 + (c0 + 1) * WPAD);
        const float4* rB0 = (const float4*)(sw4 + c0 * WPAD);
        const float4* rB1 = (const float4*)(sw4 + (c0 + 1) * WPAD);
        const float4* sv  = (const float4*)(s2s + e * HBV);
        #pragma unroll
        for (int g = 0; g < 5; g++) {
            float4 S = sv[g];
            float4 A0 = rA0[g], A1 = rA1[g], B0 = rB0[g], B1 = rB1[g];
            a3x = fmaf(A0.x, S.x, a3x); a3x = fmaf(A0.y, S.y, a3x);
            a3x = fmaf(A0.z, S.z, a3x); a3x = fmaf(A0.w, S.w, a3x);
            a3y = fmaf(A1.x, S.x, a3y); a3y = fmaf(A1.y, S.y, a3y);
            a3y = fmaf(A1.z, S.z, a3y); a3y = fmaf(A1.w, S.w, a3y);
            a4x = fmaf(B0.x, S.x, a4x); a4x = fmaf(B0.y, S.y, a4x);
            a4x = fmaf(B0.z, S.z, a4x); a4x = fmaf(B0.w, S.w, a4x);
            a4y = fmaf(B1.x, S.x, a4y); a4y = fmaf(B1.y, S.y, a4y);
            a4y = fmaf(B1.z, S.z, a4y); a4y = fmaf(B1.w, S.w, a4y);
        }
        float f3x = tanhf(a3x), f3y = tanhf(a3y);
        float f4x = tanhf(a4x), f4y = tanhf(a4y);
        e4x = expf(f4x); e4y = expf(f4y);
        float s1ex = p1.x * e4x, s1ey = p1.y * e4y;
        *(float2*)((float*)(cfs + e * CFP + c0) + 2) =
            make_float2(1.f - f3x * f3x, s1ex * (1.f - f4x * f4x));
        *(float2*)((float*)(cfs + e * CFP + c0 + 1) + 2) =
            make_float2(1.f - f3y * f3y, s1ey * (1.f - f4y * f4y));
        *(float2*)(out_vec + b * DV + c0)       = make_float2(s1ex + f3x, s1ey + f3y);
        *(float2*)(out_vec + b * DV + HBV + c0) = make_float2(s2x, s2y);
    }
    __syncthreads();

    float* jt  = out_jt + b * (DV * DV);
    float* jje = jjs + e * JJP;

    // ---- Fused k-loop: J21 (regs+BL), BR, JJ12 (smem), TR — all float2 ----
    float2 J21r[HBV];
    #pragma unroll
    for (int k = 0; k < HBV; k++) {
        float4 cf  = cfs[e * CFP + k];                    // broadcast 1wf
        float2 w1v = *(const float2*)(sw1 + k * WPAD + c0);  // uniform row
        float2 w2v = *(const float2*)(sw2 + k * WPAD + c0);
        float2 w3v = *(const float2*)(sw3 + k * WPAD + c0);
        float2 w4v = *(const float2*)(sw4 + k * WPAD + c0);

        float2 v;
        v.x = fmaf(cf.x, w1v.x, cf.y * w2v.x);
        v.y = fmaf(cf.x, w1v.y, cf.y * w2v.y);
        J21r[k] = v;
        *(float2*)(jt + (HBV + k) * DV + c0) = v;
        float2 z;
        z.x = (c0 == k)     ? e2x : 0.f;
        z.y = (c0 + 1 == k) ? e2y : 0.f;
        *(float2*)(jt + (HBV + k) * DV + HBV + c0) = z;

        float2 u;
        u.x = fmaf(cf.z, w3v.x, cf.w * w4v.x);
        u.y = fmaf(cf.z, w3v.y, cf.w * w4v.y);
        *(float2*)(jje + k * HBV + c0) = u;
        *(float2*)(jt + k * DV + HBV + c0) = make_float2(u.x * e2x, u.y * e2y);
    }
    __syncthreads();

    // ---- Top-left: TL[i, c] = e4[i] delta + sum_k JJ12[i,k] * J21[k,c] ----
    #pragma unroll 4
    for (int i = 0; i < HBV; i++) {
        const float4* rv = (const float4*)(jje + i * HBV);   // row broadcast
        float mx = 0.f, my = 0.f;
        #pragma unroll
        for (int g = 0; g < 5; g++) {
            float4 r = rv[g];
            float2 j0 = J21r[4 * g + 0], j1 = J21r[4 * g + 1];
            float2 j2 = J21r[4 * g + 2], j3 = J21r[4 * g + 3];
            mx = fmaf(r.x, j0.x, mx); my = fmaf(r.x, j0.y, my);
            mx = fmaf(r.y, j1.x, mx); my = fmaf(r.y, j1.y, my);
            mx = fmaf(r.z, j2.x, mx); my = fmaf(r.z, j2.y, my);
            mx = fmaf(r.w, j3.x, mx); my = fmaf(r.w, j3.y, my);
        }
        if (i == c0)     mx += e4x;
        if (i == c0 + 1) my += e4y;
        *(float2*)(jt + i * DV + c0) = make_float2(mx, my);
    }
}

extern "C" void kernel_launch(void* const* d_in, const int* in_sizes, int n_in,
                              void* d_out, int out_size) {
    const float* x  = (const float*)d_in[0];
    const float* w1 = (const float*)d_in[1];
    const float* w2 = (const float*)d_in[2];
    const float* w3 = (const float*)d_in[3];
    const float* w4 = (const float*)d_in[4];

    const int B = in_sizes[0] / DV;            // 65536
    float* out_vec = (float*)d_out;            // tuple element 0: (B,1,40)
    float* out_jt  = out_vec + (size_t)B * DV; // tuple element 1: (B,40,40)

    const size_t smem_bytes = SMEM_FLOATS * sizeof(float);   // 76544 B
    cudaFuncSetAttribute(ende_kernel,
                         cudaFuncAttributeMaxDynamicSharedMemorySize,
                         (int)smem_bytes);
    ende_kernel<<<B / EPB, NTHR, smem_bytes>>>(x, w1, w2, w3, w4,
                                               out_vec, out_jt);
}